// round 6
// baseline (speedup 1.0000x reference)
#include <cuda_runtime.h>
#include <cuda_bf16.h>
#include <cstdint>

#define NN 20000
#define NE 320000
#define FF 64
#define RR 8
#define HH 64
#define PP 5
#define SS 10
#define TILE 64
#define NTILES (NE / TILE)

#define INV_SQRT3 0.5773502691896258f
#define INV_SQRT2 0.7071067811865476f

// scratch (static __device__ — no allocations allowed)
__device__ float g_s1[NN * FF];
__device__ float g_v1[NN * FF * 3];
__device__ float g_As[NN * FF];
__device__ float g_Av[NN * FF * 3];
__device__ int g_hist[16];
__device__ int g_off[16];
__device__ int g_cur[16];
__device__ int g_order[NN];

// ---------------------------------------------------------------------------
__device__ __forceinline__ void red4(float* addr, float a, float b, float c, float d) {
    asm volatile("red.global.add.v4.f32 [%0], {%1,%2,%3,%4};"
                 :: "l"(__cvta_generic_to_global(addr)),
                    "f"(a), "f"(b), "f"(c), "f"(d) : "memory");
}
__device__ __forceinline__ void ldsm_x4(uint32_t* r, uint32_t addr) {
    asm volatile("ldmatrix.sync.aligned.m8n8.x4.shared.b16 {%0,%1,%2,%3}, [%4];"
                 : "=r"(r[0]), "=r"(r[1]), "=r"(r[2]), "=r"(r[3]) : "r"(addr));
}
__device__ __forceinline__ void ldsm_x4t(uint32_t* r, uint32_t addr) {
    asm volatile("ldmatrix.sync.aligned.m8n8.x4.trans.shared.b16 {%0,%1,%2,%3}, [%4];"
                 : "=r"(r[0]), "=r"(r[1]), "=r"(r[2]), "=r"(r[3]) : "r"(addr));
}
__device__ __forceinline__ void mma16816(float* c, const uint32_t* a, const uint32_t* b) {
    asm volatile("mma.sync.aligned.m16n8k16.row.col.f32.bf16.bf16.f32 "
                 "{%0,%1,%2,%3}, {%4,%5,%6,%7}, {%8,%9}, {%0,%1,%2,%3};"
                 : "+f"(c[0]), "+f"(c[1]), "+f"(c[2]), "+f"(c[3])
                 : "r"(a[0]), "r"(a[1]), "r"(a[2]), "r"(a[3]),
                   "r"(b[0]), "r"(b[1]));
}
__device__ __forceinline__ uint32_t smem_u32(const void* p) {
    uint32_t a;
    asm("{ .reg .u64 t; cvta.to.shared.u64 t, %1; cvt.u32.u64 %0, t; }"
        : "=r"(a) : "l"(p));
    return a;
}

// smem layout (byte offsets into dynamic smem)
#define ASTRIDE 72
#define BSTRIDE 328
#define TWSTRIDE 72
#define OFF_W1   0
#define OFF_BHI  2048
#define OFF_BLO  (OFF_BHI + 41984)
#define OFF_AHI  (OFF_BLO + 41984)
#define OFF_ALO  (OFF_AHI + 9216)
#define OFF_TW   (OFF_ALO + 9216)
#define DYN_BYTES (OFF_TW + 92160)   // 196608 B

// ---------------------------------------------------------------------------
// Kernel A: s1 = s @ W_lin_s ; v1 = einsum(v, W_lin_v). Zero A_s/A_v + g_hist.
// ---------------------------------------------------------------------------
__global__ __launch_bounds__(256) void knodeA(
    const float* __restrict__ s, const float* __restrict__ v,
    const float* __restrict__ Wls, const float* __restrict__ Wlv)
{
    __shared__ float sWls[FF * FF], sWlv[FF * FF];
    __shared__ float sS[4 * FF], sV[4 * FF * 3];
    if (threadIdx.x < 16) g_hist[threadIdx.x] = 0;   // benign multi-write of 0
    for (int i = threadIdx.x; i < FF * FF; i += blockDim.x) {
        sWls[i] = Wls[i];
        sWlv[i] = Wlv[i];
    }
    const int ngrp = NN / 4;
    for (int grp = blockIdx.x; grp < ngrp; grp += gridDim.x) {
        __syncthreads();
        int nbase = grp * 4;
        for (int i = threadIdx.x; i < 4 * FF; i += blockDim.x)
            sS[i] = s[nbase * FF + i];
        for (int i = threadIdx.x; i < 4 * FF * 3; i += blockDim.x)
            sV[i] = v[nbase * FF * 3 + i];
        __syncthreads();
        int nl = threadIdx.x >> 6, g = threadIdx.x & 63;
        int n = nbase + nl;
        const float* ps = sS + nl * FF;
        const float* pv = sV + nl * FF * 3;
        float as = 0.f, ax = 0.f, ay = 0.f, az = 0.f;
#pragma unroll 8
        for (int f = 0; f < FF; f++) {
            float wls = sWls[f * FF + g], wlv = sWlv[f * FF + g];
            as += ps[f] * wls;
            ax += pv[f * 3 + 0] * wlv;
            ay += pv[f * 3 + 1] * wlv;
            az += pv[f * 3 + 2] * wlv;
        }
        g_s1[n * FF + g] = as;
        g_v1[n * FF * 3 + g * 3 + 0] = ax;
        g_v1[n * FF * 3 + g * 3 + 1] = ay;
        g_v1[n * FF * 3 + g * 3 + 2] = az;
        g_As[n * FF + g] = 0.f;
        g_Av[n * FF * 3 + g * 3 + 0] = 0.f;
        g_Av[n * FF * 3 + g * 3 + 1] = 0.f;
        g_Av[n * FF * 3 + g * 3 + 2] = 0.f;
    }
}

// ---------------------------------------------------------------------------
// Species binning: histogram -> scan -> scatter (order within species is
// irrelevant; per-node work is independent).
// ---------------------------------------------------------------------------
__global__ void khist(const int* __restrict__ spec) {
    int n = blockIdx.x * blockDim.x + threadIdx.x;
    if (n < NN) atomicAdd(&g_hist[spec[n]], 1);
}
__global__ void kscan() {
    if (threadIdx.x == 0) {
        int acc = 0;
        for (int i = 0; i < SS; i++) { g_off[i] = acc; acc += g_hist[i]; }
    }
    if (threadIdx.x < 16) g_cur[threadIdx.x] = 0;
}
__global__ void kscatter(const int* __restrict__ spec) {
    int n = blockIdx.x * blockDim.x + threadIdx.x;
    if (n < NN) {
        int sp = spec[n];
        int pos = g_off[sp] + atomicAdd(&g_cur[sp], 1);
        g_order[pos] = n;
    }
}

// ---------------------------------------------------------------------------
// Kernel B: tensor-core (mma.sync bf16, hi/lo 3-pass) radial GEMM per 64-edge
// tile + CG tensor product + red.v4 scatter. Persistent, 1 block/SM.
// Epilogue gathers (s1/v1) are prefetched into registers BEFORE the GEMM so
// the ~multi-thousand-cycle HMMA phase hides the random L2 latency.
// ---------------------------------------------------------------------------
__global__ __launch_bounds__(256, 1) void kedge3(
    const float* __restrict__ Y1, const float* __restrict__ efg,
    const int* __restrict__ senders, const int* __restrict__ receivers,
    const float* __restrict__ W_rad1, const float* __restrict__ W_rad2)
{
    extern __shared__ char dsm[];
    float* sW1 = (float*)(dsm + OFF_W1);
    float* twp = (float*)(dsm + OFF_TW);
    const uint32_t uBhi = smem_u32(dsm + OFF_BHI);
    const uint32_t uBlo = smem_u32(dsm + OFF_BLO);
    const uint32_t uAhi = smem_u32(dsm + OFF_AHI);
    const uint32_t uAlo = smem_u32(dsm + OFF_ALO);

    const int tid = threadIdx.x, wid = tid >> 5, lane = tid & 31;

    for (int i = tid; i < RR * HH; i += 256) {
        int r = i / HH, j = i % HH;
        sW1[j * RR + r] = W_rad1[i];
    }
    for (int i = tid; i < HH * (PP * FF / 2); i += 256) {
        int k = i / 160, n2 = i % 160;
        float w0 = W_rad2[k * (PP * FF) + 2 * n2];
        float w1 = W_rad2[k * (PP * FF) + 2 * n2 + 1];
        __nv_bfloat16 h0 = __float2bfloat16(w0);
        __nv_bfloat16 h1 = __float2bfloat16(w1);
        __nv_bfloat16 l0 = __float2bfloat16(w0 - __bfloat162float(h0));
        __nv_bfloat16 l1 = __float2bfloat16(w1 - __bfloat162float(h1));
        uint32_t off = (uint32_t)(k * BSTRIDE + 2 * n2) * 2;
        __nv_bfloat162 ph; ph.x = h0; ph.y = h1;
        __nv_bfloat162 pl; pl.x = l0; pl.y = l1;
        *(__nv_bfloat162*)(dsm + OFF_BHI + off) = ph;
        *(__nv_bfloat162*)(dsm + OFF_BLO + off) = pl;
    }
    __syncthreads();

    const int eg = wid & 3, ch = wid >> 2;
    const int ebw = eg * 16;
    const int cbase = ch * 160;
    const int lm = lane >> 3, lr = lane & 7;
    const int arow = ebw + (lm & 1) * 8 + lr;
    const int acol0 = (lm >> 1) * 8;
    const int brow0 = (lm & 1) * 8 + lr;
    const int qq = lane & 3, eh = lane >> 2;

    const int ee = tid >> 2, fq = tid & 3, f0 = fq * 16;

    for (int t = blockIdx.x; t < NTILES; t += gridDim.x) {
        const int ebase = t * TILE;

        // ---- prefetch epilogue operands (hidden under stage A + GEMM) ----
        const int e_ep = ebase + ee;
        const int snd = senders[e_ep];
        const int rcv = receivers[e_ep];
        const float Yx = Y1[e_ep * 3 + 0];
        const float Yy = Y1[e_ep * 3 + 1];
        const float Yz = Y1[e_ep * 3 + 2];
        float4 S4[4];
        {
            const float* sp = g_s1 + (size_t)snd * FF + f0;
#pragma unroll
            for (int c4 = 0; c4 < 4; c4++) S4[c4] = *(const float4*)(sp + 4 * c4);
        }
        float4 V4[12];
        {
            const float* vp = g_v1 + (size_t)snd * FF * 3 + f0 * 3;
#pragma unroll
            for (int i = 0; i < 12; i++) V4[i] = *(const float4*)(vp + 4 * i);
        }

        // ---- stage A: h = silu(ef @ W1) -> bf16 hi/lo [64][72] ----
        {
            int e = tid & 63, jq = tid >> 6;
            const float4* efp = (const float4*)(efg + (size_t)(ebase + e) * RR);
            float4 F0 = efp[0], F1 = efp[1];
#pragma unroll
            for (int jj = 0; jj < 16; jj += 2) {
                int j = jq * 16 + jj;
                const float4* wA = (const float4*)(sW1 + j * RR);
                float4 a0 = wA[0], a1 = wA[1], b0 = wA[2], b1 = wA[3];
                float z0 = F0.x * a0.x + F0.y * a0.y + F0.z * a0.z + F0.w * a0.w +
                           F1.x * a1.x + F1.y * a1.y + F1.z * a1.z + F1.w * a1.w;
                float z1 = F0.x * b0.x + F0.y * b0.y + F0.z * b0.z + F0.w * b0.w +
                           F1.x * b1.x + F1.y * b1.y + F1.z * b1.z + F1.w * b1.w;
                float h0f = __fdividef(z0, 1.f + __expf(-z0));
                float h1f = __fdividef(z1, 1.f + __expf(-z1));
                __nv_bfloat16 h0 = __float2bfloat16(h0f);
                __nv_bfloat16 h1 = __float2bfloat16(h1f);
                __nv_bfloat16 l0 = __float2bfloat16(h0f - __bfloat162float(h0));
                __nv_bfloat16 l1 = __float2bfloat16(h1f - __bfloat162float(h1));
                uint32_t off = (uint32_t)(e * ASTRIDE + j) * 2;
                __nv_bfloat162 ph; ph.x = h0; ph.y = h1;
                __nv_bfloat162 pl; pl.x = l0; pl.y = l1;
                *(__nv_bfloat162*)(dsm + OFF_AHI + off) = ph;
                *(__nv_bfloat162*)(dsm + OFF_ALO + off) = pl;
            }
        }
        __syncthreads();

        // ---- GEMM: tw = h @ W2, 3 bf16 passes (hi*hi, hi*lo, lo*hi) ----
        {
            float acc[20][4];
#pragma unroll
            for (int n = 0; n < 20; n++) {
                acc[n][0] = 0.f; acc[n][1] = 0.f; acc[n][2] = 0.f; acc[n][3] = 0.f;
            }
            const uint32_t Asel[3] = {uAhi, uAhi, uAlo};
            const uint32_t Bsel[3] = {uBhi, uBlo, uBhi};
#pragma unroll
            for (int pass = 0; pass < 3; pass++) {
                uint32_t Ab = Asel[pass], Bb = Bsel[pass];
#pragma unroll
                for (int k = 0; k < 4; k++) {
                    uint32_t a[4];
                    ldsm_x4(a, Ab + (uint32_t)(arow * ASTRIDE + k * 16 + acol0) * 2);
#pragma unroll
                    for (int nt2 = 0; nt2 < 10; nt2++) {
                        uint32_t b[4];
                        ldsm_x4t(b, Bb + (uint32_t)((k * 16 + brow0) * BSTRIDE +
                                                    cbase + nt2 * 16 + acol0) * 2);
                        mma16816(acc[2 * nt2], a, b);
                        mma16816(acc[2 * nt2 + 1], a, b + 2);
                    }
                }
            }
#pragma unroll
            for (int nt = 0; nt < 20; nt++) {
                int c = cbase + nt * 8 + 2 * qq;
                int p = c >> 6, f = c & 63;
                float* dst = twp + (size_t)(p * 64 + ebw + eh) * TWSTRIDE + f;
                float2 lo; lo.x = acc[nt][0]; lo.y = acc[nt][1];
                float2 hi; hi.x = acc[nt][2]; hi.y = acc[nt][3];
                *(float2*)dst = lo;
                *(float2*)(dst + 8 * TWSTRIDE) = hi;
            }
        }
        __syncthreads();

        // ---- epilogue: CG tensor product + scatter (thread = edge x f-quad) --
        {
            float4 T[5][4];
#pragma unroll
            for (int p = 0; p < 5; p++) {
                const float* tb = twp + (size_t)(p * 64 + ee) * TWSTRIDE + f0;
#pragma unroll
                for (int c4 = 0; c4 < 4; c4++)
                    T[p][c4] = *(const float4*)(tb + 4 * c4);
            }
            const float* sf = (const float*)S4;
            const float* vvf = (const float*)V4;
            float* Ap = g_As + (size_t)rcv * FF + f0;
            float* Vp = g_Av + (size_t)rcv * FF * 3 + f0 * 3;

#pragma unroll
            for (int c4 = 0; c4 < 4; c4++) {
                float ms[4], mv[12];
#pragma unroll
                for (int i = 0; i < 4; i++) {
                    int fi = 4 * c4 + i;
                    float tw0 = ((const float*)T[0])[fi];
                    float tw1 = ((const float*)T[1])[fi];
                    float tw2 = ((const float*)T[2])[fi];
                    float tw3 = ((const float*)T[3])[fi];
                    float tw4 = ((const float*)T[4])[fi];
                    float ssf = sf[fi];
                    float vx = vvf[3 * fi + 0];
                    float vy = vvf[3 * fi + 1];
                    float vz = vvf[3 * fi + 2];
                    float dot = vx * Yx + vy * Yy + vz * Yz;
                    float cx = vy * Yz - vz * Yy;
                    float cy = vz * Yx - vx * Yz;
                    float cz = vx * Yy - vy * Yx;
                    ms[i] = tw0 * ssf + tw1 * dot * INV_SQRT3;
                    float t2s = tw2 * ssf;
                    float t4 = tw4 * INV_SQRT2;
                    mv[3 * i + 0] = t2s * Yx + tw3 * vx + t4 * cx;
                    mv[3 * i + 1] = t2s * Yy + tw3 * vy + t4 * cy;
                    mv[3 * i + 2] = t2s * Yz + tw3 * vz + t4 * cz;
                }
                red4(Ap + 4 * c4, ms[0], ms[1], ms[2], ms[3]);
                red4(Vp + 12 * c4 + 0, mv[0], mv[1], mv[2], mv[3]);
                red4(Vp + 12 * c4 + 4, mv[4], mv[5], mv[6], mv[7]);
                red4(Vp + 12 * c4 + 8, mv[8], mv[9], mv[10], mv[11]);
            }
        }
        __syncthreads();
    }
}

// ---------------------------------------------------------------------------
// Kernel C: node post — processes nodes in species order (g_order) so the
// per-species skip matrices W_sc hit L1 instead of streaming from L2.
// ---------------------------------------------------------------------------
__global__ __launch_bounds__(256, 2) void knodeC(
    const float* __restrict__ s, const float* __restrict__ v,
    const int* __restrict__ spec,
    const float* __restrict__ W_sc_s, const float* __restrict__ W_sc_v,
    const float* __restrict__ W_int_s, const float* __restrict__ W_int_v,
    const float* __restrict__ w_prod_s, const float* __restrict__ w_prod_v,
    const float* __restrict__ W_prod_s, const float* __restrict__ W_prod_v,
    const float* __restrict__ W_read,
    float* __restrict__ out_node, float* __restrict__ out_s,
    float* __restrict__ out_v)
{
    extern __shared__ float sm[];
    float* sWis = sm;
    float* sWiv = sWis + FF * FF;
    float* sWps = sWiv + FF * FF;
    float* sWpv = sWps + FF * FF;
    float* sWr  = sWpv + FF * FF;
    float* sAs  = sWr + FF;
    float* sAv  = sAs + 4 * FF;
    float* sSin = sAv + 4 * FF * 3;
    float* sVin = sSin + 4 * FF;
    float* sBs  = sVin + 4 * FF * 3;
    float* sBv  = sBs + 4 * FF;
    float* sRed = sBv + 4 * FF * 3;
    __shared__ int sNode[4], sSpec[4];

    for (int i = threadIdx.x; i < FF * FF; i += blockDim.x) {
        sWis[i] = W_int_s[i];
        sWiv[i] = W_int_v[i];
        sWps[i] = W_prod_s[i];
        sWpv[i] = W_prod_v[i];
    }
    if (threadIdx.x < FF) sWr[threadIdx.x] = W_read[threadIdx.x];

    const int ngrp = NN / 4;
    for (int grp = blockIdx.x; grp < ngrp; grp += gridDim.x) {
        __syncthreads();
        int obase = grp * 4;
        if (threadIdx.x < 4) {
            int nn = g_order[obase + threadIdx.x];
            sNode[threadIdx.x] = nn;
            sSpec[threadIdx.x] = spec[nn];
        }
        __syncthreads();
        for (int i = threadIdx.x; i < 4 * FF; i += blockDim.x) {
            int node = sNode[i >> 6], f = i & 63;
            sAs[i] = g_As[node * FF + f];
            sSin[i] = s[node * FF + f];
        }
        for (int i = threadIdx.x; i < 4 * FF * 3; i += blockDim.x) {
            int node = sNode[i / (FF * 3)], r = i % (FF * 3);
            sAv[i] = g_Av[node * FF * 3 + r];
            sVin[i] = v[node * FF * 3 + r];
        }
        __syncthreads();

        int nl = threadIdx.x >> 6, g = threadIdx.x & 63;
        int n = sNode[nl];
        int sp = sSpec[nl];
        const float* Wscs = W_sc_s + sp * FF * FF;
        const float* Wscv = W_sc_v + sp * FF * FF;
        const float* pAs = sAs + nl * FF;
        const float* pAv = sAv + nl * FF * 3;
        const float* pS = sSin + nl * FF;
        const float* pV = sVin + nl * FF * 3;

        float as = 0.f, avx = 0.f, avy = 0.f, avz = 0.f;
        float scs = 0.f, scvx = 0.f, scvy = 0.f, scvz = 0.f;
#pragma unroll 4
        for (int f = 0; f < FF; f++) {
            float wis = sWis[f * FF + g], wiv = sWiv[f * FF + g];
            float wss = __ldg(Wscs + f * FF + g);
            float wsv = __ldg(Wscv + f * FF + g);
            as += pAs[f] * wis;
            avx += pAv[f * 3 + 0] * wiv;
            avy += pAv[f * 3 + 1] * wiv;
            avz += pAv[f * 3 + 2] * wiv;
            scs += pS[f] * wss;
            scvx += pV[f * 3 + 0] * wsv;
            scvy += pV[f * 3 + 1] * wsv;
            scvz += pV[f * 3 + 2] * wsv;
        }
        const float inv = 0.25f;
        as *= inv; avx *= inv; avy *= inv; avz *= inv;

        const float* wps = w_prod_s + sp * 5 * FF;
        const float* wpv = w_prod_v + sp * 4 * FF;
        float d = avx * avx + avy * avy + avz * avz;
        float as2 = as * as;
        float Bs = wps[0 * FF + g] * as + wps[1 * FF + g] * as2 +
                   wps[2 * FF + g] * d + wps[3 * FF + g] * as2 * as +
                   wps[4 * FF + g] * as * d;
        float gv = wpv[0 * FF + g] + wpv[1 * FF + g] * as +
                   wpv[2 * FF + g] * as2 + wpv[3 * FF + g] * d;
        sBs[nl * FF + g] = Bs;
        sBv[nl * FF * 3 + g * 3 + 0] = gv * avx;
        sBv[nl * FF * 3 + g * 3 + 1] = gv * avy;
        sBv[nl * FF * 3 + g * 3 + 2] = gv * avz;
        __syncthreads();

        const float* pBs = sBs + nl * FF;
        const float* pBv = sBv + nl * FF * 3;
        float so = scs, vox = scvx, voy = scvy, voz = scvz;
#pragma unroll 4
        for (int f = 0; f < FF; f++) {
            float wp = sWps[f * FF + g], wv = sWpv[f * FF + g];
            so += pBs[f] * wp;
            vox += pBv[f * 3 + 0] * wv;
            voy += pBv[f * 3 + 1] * wv;
            voz += pBv[f * 3 + 2] * wv;
        }
        out_s[n * FF + g] = so;
        out_v[n * FF * 3 + g * 3 + 0] = vox;
        out_v[n * FF * 3 + g * 3 + 1] = voy;
        out_v[n * FF * 3 + g * 3 + 2] = voz;

        float r = so * sWr[g];
#pragma unroll
        for (int o = 16; o > 0; o >>= 1) r += __shfl_down_sync(0xffffffffu, r, o);
        if ((threadIdx.x & 31) == 0) sRed[threadIdx.x >> 5] = r;
        __syncthreads();
        if ((threadIdx.x & 63) == 0)
            out_node[n] = sRed[threadIdx.x >> 5] + sRed[(threadIdx.x >> 5) + 1];
    }
}

// ---------------------------------------------------------------------------
extern "C" void kernel_launch(void* const* d_in, const int* in_sizes, int n_in,
                              void* d_out, int out_size)
{
    const float* s    = (const float*)d_in[0];
    const float* v    = (const float*)d_in[1];
    const float* Y1   = (const float*)d_in[2];
    const float* ef   = (const float*)d_in[3];
    const int*   spec = (const int*)d_in[4];
    const int*   snd  = (const int*)d_in[5];
    const int*   rcv  = (const int*)d_in[6];
    const float* Wls  = (const float*)d_in[7];
    const float* Wlv  = (const float*)d_in[8];
    const float* Wscs = (const float*)d_in[9];
    const float* Wscv = (const float*)d_in[10];
    const float* Wr1  = (const float*)d_in[11];
    const float* Wr2  = (const float*)d_in[12];
    const float* Wis  = (const float*)d_in[13];
    const float* Wiv  = (const float*)d_in[14];
    const float* wps  = (const float*)d_in[15];
    const float* wpv  = (const float*)d_in[16];
    const float* Wps  = (const float*)d_in[17];
    const float* Wpv  = (const float*)d_in[18];
    const float* Wrd  = (const float*)d_in[19];

    float* out = (float*)d_out;
    float* out_node = out;
    float* out_s = out + NN;
    float* out_v = out + NN + NN * FF;

    const int smemC = (4 * FF * FF + FF + 4 * FF * 2 + 4 * FF * 3 * 2 +
                       4 * FF + 4 * FF * 3 + 8) * (int)sizeof(float);
    cudaFuncSetAttribute(kedge3, cudaFuncAttributeMaxDynamicSharedMemorySize, DYN_BYTES);
    cudaFuncSetAttribute(knodeC, cudaFuncAttributeMaxDynamicSharedMemorySize, smemC);

    knodeA<<<592, 256>>>(s, v, Wls, Wlv);
    khist<<<(NN + 255) / 256, 256>>>(spec);
    kscan<<<1, 32>>>();
    kscatter<<<(NN + 255) / 256, 256>>>(spec);
    kedge3<<<152, 256, DYN_BYTES>>>(Y1, ef, snd, rcv, Wr1, Wr2);
    knodeC<<<296, 256, smemC>>>(s, v, spec, Wscs, Wscv, Wis, Wiv,
                                wps, wpv, Wps, Wpv, Wrd,
                                out_node, out_s, out_v);
}

// round 7
// speedup vs baseline: 1.0585x; 1.0585x over previous
#include <cuda_runtime.h>
#include <cuda_bf16.h>
#include <cstdint>

#define NN 20000
#define NE 320000
#define FF 64
#define RR 8
#define HH 64
#define PP 5
#define TILE 64
#define NTILES (NE / TILE)

#define INV_SQRT3 0.5773502691896258f
#define INV_SQRT2 0.7071067811865476f

// scratch (static __device__ — no allocations allowed)
__device__ float g_s1[NN * FF];
__device__ float g_v1[NN * FF * 3];
__device__ float g_As[NN * FF];
__device__ float g_Av[NN * FF * 3];

// ---------------------------------------------------------------------------
__device__ __forceinline__ void red2(float* addr, float a, float b) {
    asm volatile("red.global.add.v2.f32 [%0], {%1,%2};"
                 :: "l"(__cvta_generic_to_global(addr)), "f"(a), "f"(b) : "memory");
}
__device__ __forceinline__ void ldsm_x4(uint32_t* r, uint32_t addr) {
    asm volatile("ldmatrix.sync.aligned.m8n8.x4.shared.b16 {%0,%1,%2,%3}, [%4];"
                 : "=r"(r[0]), "=r"(r[1]), "=r"(r[2]), "=r"(r[3]) : "r"(addr));
}
__device__ __forceinline__ void ldsm_x4t(uint32_t* r, uint32_t addr) {
    asm volatile("ldmatrix.sync.aligned.m8n8.x4.trans.shared.b16 {%0,%1,%2,%3}, [%4];"
                 : "=r"(r[0]), "=r"(r[1]), "=r"(r[2]), "=r"(r[3]) : "r"(addr));
}
__device__ __forceinline__ void mma16816(float* c, const uint32_t* a, const uint32_t* b) {
    asm volatile("mma.sync.aligned.m16n8k16.row.col.f32.bf16.bf16.f32 "
                 "{%0,%1,%2,%3}, {%4,%5,%6,%7}, {%8,%9}, {%0,%1,%2,%3};"
                 : "+f"(c[0]), "+f"(c[1]), "+f"(c[2]), "+f"(c[3])
                 : "r"(a[0]), "r"(a[1]), "r"(a[2]), "r"(a[3]),
                   "r"(b[0]), "r"(b[1]));
}
__device__ __forceinline__ uint32_t smem_u32(const void* p) {
    uint32_t a;
    asm("{ .reg .u64 t; cvta.to.shared.u64 t, %1; cvt.u32.u64 %0, t; }"
        : "=r"(a) : "l"(p));
    return a;
}

// smem layout (byte offsets into dynamic smem)
#define ASTRIDE 72
#define BSTRIDE 328
#define OFF_W1   0                       // 512 floats (2048 B)
#define OFF_BHI  2048                    // 64*328*2 = 41984 B
#define OFF_BLO  (OFF_BHI + 41984)
#define OFF_A    (OFF_BLO + 41984)       // 2 bufs x (hi 9216 + lo 9216)
#define ABUF_SZ  18432
#define DYN_BYTES (OFF_A + 2 * ABUF_SZ)  // 122880 B

// ---------------------------------------------------------------------------
// Kernel A: s1 = s @ W_lin_s ; v1 = einsum(v, W_lin_v). Zero A_s/A_v.
// ---------------------------------------------------------------------------
__global__ __launch_bounds__(256) void knodeA(
    const float* __restrict__ s, const float* __restrict__ v,
    const float* __restrict__ Wls, const float* __restrict__ Wlv)
{
    __shared__ float sWls[FF * FF], sWlv[FF * FF];
    __shared__ float sS[4 * FF], sV[4 * FF * 3];
    for (int i = threadIdx.x; i < FF * FF; i += blockDim.x) {
        sWls[i] = Wls[i];
        sWlv[i] = Wlv[i];
    }
    const int ngrp = NN / 4;
    for (int grp = blockIdx.x; grp < ngrp; grp += gridDim.x) {
        __syncthreads();
        int nbase = grp * 4;
        for (int i = threadIdx.x; i < 4 * FF; i += blockDim.x)
            sS[i] = s[nbase * FF + i];
        for (int i = threadIdx.x; i < 4 * FF * 3; i += blockDim.x)
            sV[i] = v[nbase * FF * 3 + i];
        __syncthreads();
        int nl = threadIdx.x >> 6, g = threadIdx.x & 63;
        int n = nbase + nl;
        const float* ps = sS + nl * FF;
        const float* pv = sV + nl * FF * 3;
        float as = 0.f, ax = 0.f, ay = 0.f, az = 0.f;
#pragma unroll 8
        for (int f = 0; f < FF; f++) {
            float wls = sWls[f * FF + g], wlv = sWlv[f * FF + g];
            as += ps[f] * wls;
            ax += pv[f * 3 + 0] * wlv;
            ay += pv[f * 3 + 1] * wlv;
            az += pv[f * 3 + 2] * wlv;
        }
        g_s1[n * FF + g] = as;
        g_v1[n * FF * 3 + g * 3 + 0] = ax;
        g_v1[n * FF * 3 + g * 3 + 1] = ay;
        g_v1[n * FF * 3 + g * 3 + 2] = az;
        g_As[n * FF + g] = 0.f;
        g_Av[n * FF * 3 + g * 3 + 0] = 0.f;
        g_Av[n * FF * 3 + g * 3 + 1] = 0.f;
        g_Av[n * FF * 3 + g * 3 + 2] = 0.f;
    }
}

// ---------------------------------------------------------------------------
// Kernel B: mma.sync bf16 hi/lo 3-pass GEMM with warp-owned path columns:
// warp (eg,ch) computes tw[p][e in 16][f in ch*32..+32] for ALL p, so the CG
// tensor product runs directly from accumulator registers (no smem round-trip).
// A tile double-buffered: stage A(t+1) overlaps epilogue(t); 1 sync per tile.
// ---------------------------------------------------------------------------
__global__ __launch_bounds__(256, 1) void kedge4(
    const float* __restrict__ Y1, const float* __restrict__ efg,
    const int* __restrict__ senders, const int* __restrict__ receivers,
    const float* __restrict__ W_rad1, const float* __restrict__ W_rad2)
{
    extern __shared__ char dsm[];
    float* sW1 = (float*)(dsm + OFF_W1);
    const uint32_t uBhi = smem_u32(dsm + OFF_BHI);
    const uint32_t uBlo = smem_u32(dsm + OFF_BLO);
    const uint32_t uA0 = smem_u32(dsm + OFF_A);

    const int tid = threadIdx.x, wid = tid >> 5, lane = tid & 31;

    // --- one-time staging: W1 transposed, W2 -> B hi/lo [64][328] bf16 ---
    for (int i = tid; i < RR * HH; i += 256) {
        int r = i / HH, j = i % HH;
        sW1[j * RR + r] = W_rad1[i];
    }
    for (int i = tid; i < HH * (PP * FF / 2); i += 256) {
        int k = i / 160, n2 = i % 160;
        float w0 = W_rad2[k * (PP * FF) + 2 * n2];
        float w1 = W_rad2[k * (PP * FF) + 2 * n2 + 1];
        __nv_bfloat16 h0 = __float2bfloat16(w0);
        __nv_bfloat16 h1 = __float2bfloat16(w1);
        __nv_bfloat16 l0 = __float2bfloat16(w0 - __bfloat162float(h0));
        __nv_bfloat16 l1 = __float2bfloat16(w1 - __bfloat162float(h1));
        uint32_t off = (uint32_t)(k * BSTRIDE + 2 * n2) * 2;
        __nv_bfloat162 ph; ph.x = h0; ph.y = h1;
        __nv_bfloat162 pl; pl.x = l0; pl.y = l1;
        *(__nv_bfloat162*)(dsm + OFF_BHI + off) = ph;
        *(__nv_bfloat162*)(dsm + OFF_BLO + off) = pl;
    }

    const int eg = wid & 3, ch = wid >> 2;
    const int ebw = eg * 16;
    const int lm = lane >> 3, lr = lane & 7;
    const int arow = ebw + (lm & 1) * 8 + lr;
    const int acol0 = (lm >> 1) * 8;
    const int brow0 = (lm & 1) * 8 + lr;
    const int qq = lane & 3, eh = lane >> 2;

    // stage A tile (h = silu(ef @ W1) -> bf16 hi/lo [64][72]) into buffer b
    auto stageA = [&](int t, int buf) {
        char* ab = dsm + OFF_A + buf * ABUF_SZ;
        int e = tid & 63, jq = tid >> 6;
        const float4* efp = (const float4*)(efg + (size_t)(t * TILE + e) * RR);
        float4 F0 = efp[0], F1 = efp[1];
#pragma unroll
        for (int jj = 0; jj < 16; jj += 2) {
            int j = jq * 16 + jj;
            const float4* wA = (const float4*)(sW1 + j * RR);
            float4 a0 = wA[0], a1 = wA[1], b0 = wA[2], b1 = wA[3];
            float z0 = F0.x * a0.x + F0.y * a0.y + F0.z * a0.z + F0.w * a0.w +
                       F1.x * a1.x + F1.y * a1.y + F1.z * a1.z + F1.w * a1.w;
            float z1 = F0.x * b0.x + F0.y * b0.y + F0.z * b0.z + F0.w * b0.w +
                       F1.x * b1.x + F1.y * b1.y + F1.z * b1.z + F1.w * b1.w;
            float h0f = __fdividef(z0, 1.f + __expf(-z0));
            float h1f = __fdividef(z1, 1.f + __expf(-z1));
            __nv_bfloat16 h0 = __float2bfloat16(h0f);
            __nv_bfloat16 h1 = __float2bfloat16(h1f);
            __nv_bfloat16 l0 = __float2bfloat16(h0f - __bfloat162float(h0));
            __nv_bfloat16 l1 = __float2bfloat16(h1f - __bfloat162float(h1));
            uint32_t off = (uint32_t)(e * ASTRIDE + j) * 2;
            __nv_bfloat162 ph; ph.x = h0; ph.y = h1;
            __nv_bfloat162 pl; pl.x = l0; pl.y = l1;
            *(__nv_bfloat162*)(ab + off) = ph;
            *(__nv_bfloat162*)(ab + 9216 + off) = pl;
        }
    };

    const int t0 = blockIdx.x;
    if (t0 < NTILES) stageA(t0, 0);
    __syncthreads();

    int it = 0;
    for (int t = t0; t < NTILES; t += gridDim.x, it++) {
        const int buf = it & 1;
        const uint32_t uAhi = uA0 + buf * ABUF_SZ;
        const uint32_t uAlo = uAhi + 9216;

        // ---- GEMM: acc[p][fsub][4], cols = p*64 + ch*32 + fsub*8 ----
        float acc[PP][4][4];
#pragma unroll
        for (int p = 0; p < PP; p++)
#pragma unroll
            for (int fs = 0; fs < 4; fs++) {
                acc[p][fs][0] = 0.f; acc[p][fs][1] = 0.f;
                acc[p][fs][2] = 0.f; acc[p][fs][3] = 0.f;
            }
#pragma unroll
        for (int pass = 0; pass < 3; pass++) {
            uint32_t Ab = (pass == 2) ? uAlo : uAhi;
            uint32_t Bb = (pass == 1) ? uBlo : uBhi;
#pragma unroll
            for (int k = 0; k < 4; k++) {
                uint32_t a[4];
                ldsm_x4(a, Ab + (uint32_t)(arow * ASTRIDE + k * 16 + acol0) * 2);
#pragma unroll
                for (int p = 0; p < PP; p++) {
#pragma unroll
                    for (int fs2 = 0; fs2 < 2; fs2++) {
                        int col = p * 64 + ch * 32 + fs2 * 16;
                        uint32_t b[4];
                        ldsm_x4t(b, Bb + (uint32_t)((k * 16 + brow0) * BSTRIDE +
                                                    col + acol0) * 2);
                        mma16816(acc[p][fs2 * 2], a, b);
                        mma16816(acc[p][fs2 * 2 + 1], a, b + 2);
                    }
                }
            }
        }

        // ---- stage next tile's A (overlaps epilogue; consumed after sync) ----
        int tn = t + gridDim.x;
        if (tn < NTILES) stageA(tn, buf ^ 1);

        // ---- epilogue straight from accumulators ----
#pragma unroll
        for (int eidx = 0; eidx < 2; eidx++) {
            int e = t * TILE + ebw + eh + eidx * 8;
            int snd = senders[e], rcv = receivers[e];
            float Yx = Y1[e * 3 + 0], Yy = Y1[e * 3 + 1], Yz = Y1[e * 3 + 2];

            // gather s1/v1 for this thread's 8 f-values (4 fsub x 2 cols)
            float2 sv[4], vv[4][3];
            const float* sp = g_s1 + (size_t)snd * FF;
            const float* vp = g_v1 + (size_t)snd * FF * 3;
#pragma unroll
            for (int fs = 0; fs < 4; fs++) {
                int f = ch * 32 + fs * 8 + 2 * qq;
                sv[fs] = *(const float2*)(sp + f);
                const float* vq = vp + f * 3;
                vv[fs][0] = *(const float2*)(vq + 0);
                vv[fs][1] = *(const float2*)(vq + 2);
                vv[fs][2] = *(const float2*)(vq + 4);
            }

            float* Ap = g_As + (size_t)rcv * FF;
            float* Vp = g_Av + (size_t)rcv * FF * 3;
#pragma unroll
            for (int fs = 0; fs < 4; fs++) {
                int f = ch * 32 + fs * 8 + 2 * qq;
                float ms[2], mv[6];
#pragma unroll
                for (int c = 0; c < 2; c++) {
                    float tw0 = acc[0][fs][eidx * 2 + c];
                    float tw1 = acc[1][fs][eidx * 2 + c];
                    float tw2 = acc[2][fs][eidx * 2 + c];
                    float tw3 = acc[3][fs][eidx * 2 + c];
                    float tw4 = acc[4][fs][eidx * 2 + c];
                    float ssf = c ? sv[fs].y : sv[fs].x;
                    float vx = c ? vv[fs][1].y : vv[fs][0].x;
                    float vy = c ? vv[fs][2].x : vv[fs][0].y;
                    float vz = c ? vv[fs][2].y : vv[fs][1].x;
                    float dot = vx * Yx + vy * Yy + vz * Yz;
                    float cx = vy * Yz - vz * Yy;
                    float cy = vz * Yx - vx * Yz;
                    float cz = vx * Yy - vy * Yx;
                    ms[c] = tw0 * ssf + tw1 * dot * INV_SQRT3;
                    float t2s = tw2 * ssf;
                    float t4 = tw4 * INV_SQRT2;
                    mv[3 * c + 0] = t2s * Yx + tw3 * vx + t4 * cx;
                    mv[3 * c + 1] = t2s * Yy + tw3 * vy + t4 * cy;
                    mv[3 * c + 2] = t2s * Yz + tw3 * vz + t4 * cz;
                }
                red2(Ap + f, ms[0], ms[1]);
                float* vq = Vp + f * 3;
                red2(vq + 0, mv[0], mv[1]);
                red2(vq + 2, mv[2], mv[3]);
                red2(vq + 4, mv[4], mv[5]);
            }
        }
        __syncthreads();
    }
}

// ---------------------------------------------------------------------------
// Kernel C: node post: W_int + species skip + product basis + W_prod + readout
// ---------------------------------------------------------------------------
__global__ __launch_bounds__(256, 2) void knodeC(
    const float* __restrict__ s, const float* __restrict__ v,
    const int* __restrict__ spec,
    const float* __restrict__ W_sc_s, const float* __restrict__ W_sc_v,
    const float* __restrict__ W_int_s, const float* __restrict__ W_int_v,
    const float* __restrict__ w_prod_s, const float* __restrict__ w_prod_v,
    const float* __restrict__ W_prod_s, const float* __restrict__ W_prod_v,
    const float* __restrict__ W_read,
    float* __restrict__ out_node, float* __restrict__ out_s,
    float* __restrict__ out_v)
{
    extern __shared__ float sm[];
    float* sWis = sm;
    float* sWiv = sWis + FF * FF;
    float* sWps = sWiv + FF * FF;
    float* sWpv = sWps + FF * FF;
    float* sWr  = sWpv + FF * FF;
    float* sAs  = sWr + FF;
    float* sAv  = sAs + 4 * FF;
    float* sSin = sAv + 4 * FF * 3;
    float* sVin = sSin + 4 * FF;
    float* sBs  = sVin + 4 * FF * 3;
    float* sBv  = sBs + 4 * FF;
    float* sRed = sBv + 4 * FF * 3;
    __shared__ int sSpec[4];

    for (int i = threadIdx.x; i < FF * FF; i += blockDim.x) {
        sWis[i] = W_int_s[i];
        sWiv[i] = W_int_v[i];
        sWps[i] = W_prod_s[i];
        sWpv[i] = W_prod_v[i];
    }
    if (threadIdx.x < FF) sWr[threadIdx.x] = W_read[threadIdx.x];

    const int ngrp = NN / 4;
    for (int grp = blockIdx.x; grp < ngrp; grp += gridDim.x) {
        __syncthreads();
        int nbase = grp * 4;
        for (int i = threadIdx.x; i < 4 * FF; i += blockDim.x) {
            sAs[i] = g_As[nbase * FF + i];
            sSin[i] = s[nbase * FF + i];
        }
        for (int i = threadIdx.x; i < 4 * FF * 3; i += blockDim.x) {
            sAv[i] = g_Av[nbase * FF * 3 + i];
            sVin[i] = v[nbase * FF * 3 + i];
        }
        if (threadIdx.x < 4) sSpec[threadIdx.x] = spec[nbase + threadIdx.x];
        __syncthreads();

        int nl = threadIdx.x >> 6, g = threadIdx.x & 63;
        int n = nbase + nl;
        int sp = sSpec[nl];
        const float* Wscs = W_sc_s + sp * FF * FF;
        const float* Wscv = W_sc_v + sp * FF * FF;
        const float* pAs = sAs + nl * FF;
        const float* pAv = sAv + nl * FF * 3;
        const float* pS = sSin + nl * FF;
        const float* pV = sVin + nl * FF * 3;

        float as = 0.f, avx = 0.f, avy = 0.f, avz = 0.f;
        float scs = 0.f, scvx = 0.f, scvy = 0.f, scvz = 0.f;
#pragma unroll 4
        for (int f = 0; f < FF; f++) {
            float wis = sWis[f * FF + g], wiv = sWiv[f * FF + g];
            float wss = __ldg(Wscs + f * FF + g);
            float wsv = __ldg(Wscv + f * FF + g);
            as += pAs[f] * wis;
            avx += pAv[f * 3 + 0] * wiv;
            avy += pAv[f * 3 + 1] * wiv;
            avz += pAv[f * 3 + 2] * wiv;
            scs += pS[f] * wss;
            scvx += pV[f * 3 + 0] * wsv;
            scvy += pV[f * 3 + 1] * wsv;
            scvz += pV[f * 3 + 2] * wsv;
        }
        const float inv = 0.25f;
        as *= inv; avx *= inv; avy *= inv; avz *= inv;

        const float* wps = w_prod_s + sp * 5 * FF;
        const float* wpv = w_prod_v + sp * 4 * FF;
        float d = avx * avx + avy * avy + avz * avz;
        float as2 = as * as;
        float Bs = wps[0 * FF + g] * as + wps[1 * FF + g] * as2 +
                   wps[2 * FF + g] * d + wps[3 * FF + g] * as2 * as +
                   wps[4 * FF + g] * as * d;
        float gv = wpv[0 * FF + g] + wpv[1 * FF + g] * as +
                   wpv[2 * FF + g] * as2 + wpv[3 * FF + g] * d;
        sBs[nl * FF + g] = Bs;
        sBv[nl * FF * 3 + g * 3 + 0] = gv * avx;
        sBv[nl * FF * 3 + g * 3 + 1] = gv * avy;
        sBv[nl * FF * 3 + g * 3 + 2] = gv * avz;
        __syncthreads();

        const float* pBs = sBs + nl * FF;
        const float* pBv = sBv + nl * FF * 3;
        float so = scs, vox = scvx, voy = scvy, voz = scvz;
#pragma unroll 4
        for (int f = 0; f < FF; f++) {
            float wp = sWps[f * FF + g], wv = sWpv[f * FF + g];
            so += pBs[f] * wp;
            vox += pBv[f * 3 + 0] * wv;
            voy += pBv[f * 3 + 1] * wv;
            voz += pBv[f * 3 + 2] * wv;
        }
        out_s[n * FF + g] = so;
        out_v[n * FF * 3 + g * 3 + 0] = vox;
        out_v[n * FF * 3 + g * 3 + 1] = voy;
        out_v[n * FF * 3 + g * 3 + 2] = voz;

        float r = so * sWr[g];
#pragma unroll
        for (int o = 16; o > 0; o >>= 1) r += __shfl_down_sync(0xffffffffu, r, o);
        if ((threadIdx.x & 31) == 0) sRed[threadIdx.x >> 5] = r;
        __syncthreads();
        if ((threadIdx.x & 63) == 0)
            out_node[n] = sRed[threadIdx.x >> 5] + sRed[(threadIdx.x >> 5) + 1];
    }
}

// ---------------------------------------------------------------------------
extern "C" void kernel_launch(void* const* d_in, const int* in_sizes, int n_in,
                              void* d_out, int out_size)
{
    const float* s    = (const float*)d_in[0];
    const float* v    = (const float*)d_in[1];
    const float* Y1   = (const float*)d_in[2];
    const float* ef   = (const float*)d_in[3];
    const int*   spec = (const int*)d_in[4];
    const int*   snd  = (const int*)d_in[5];
    const int*   rcv  = (const int*)d_in[6];
    const float* Wls  = (const float*)d_in[7];
    const float* Wlv  = (const float*)d_in[8];
    const float* Wscs = (const float*)d_in[9];
    const float* Wscv = (const float*)d_in[10];
    const float* Wr1  = (const float*)d_in[11];
    const float* Wr2  = (const float*)d_in[12];
    const float* Wis  = (const float*)d_in[13];
    const float* Wiv  = (const float*)d_in[14];
    const float* wps  = (const float*)d_in[15];
    const float* wpv  = (const float*)d_in[16];
    const float* Wps  = (const float*)d_in[17];
    const float* Wpv  = (const float*)d_in[18];
    const float* Wrd  = (const float*)d_in[19];

    float* out = (float*)d_out;
    float* out_node = out;
    float* out_s = out + NN;
    float* out_v = out + NN + NN * FF;

    const int smemC = (4 * FF * FF + FF + 4 * FF * 2 + 4 * FF * 3 * 2 +
                       4 * FF + 4 * FF * 3 + 8) * (int)sizeof(float);
    cudaFuncSetAttribute(kedge4, cudaFuncAttributeMaxDynamicSharedMemorySize, DYN_BYTES);
    cudaFuncSetAttribute(knodeC, cudaFuncAttributeMaxDynamicSharedMemorySize, smemC);

    knodeA<<<592, 256>>>(s, v, Wls, Wlv);
    kedge4<<<152, 256, DYN_BYTES>>>(Y1, ef, snd, rcv, Wr1, Wr2);
    knodeC<<<296, 256, smemC>>>(s, v, spec, Wscs, Wscv, Wis, Wiv,
                                wps, wpv, Wps, Wpv, Wrd,
                                out_node, out_s, out_v);
}

// round 8
// speedup vs baseline: 1.1496x; 1.0860x over previous
#include <cuda_runtime.h>
#include <cuda_bf16.h>
#include <cstdint>

#define NN 20000
#define NE 320000
#define FF 64
#define RR 8
#define HH 64
#define PP 5
#define TILE 64
#define NTILES (NE / TILE)

#define INV_SQRT3 0.5773502691896258f
#define INV_SQRT2 0.7071067811865476f

// scratch (static __device__ — no allocations allowed)
__device__ float g_s1[NN * FF];
__device__ float g_v1[NN * FF * 3];
__device__ float g_As[NN * FF];
__device__ float g_Av[NN * FF * 3];

// ---------------------------------------------------------------------------
__device__ __forceinline__ void red4(float* addr, float a, float b, float c, float d) {
    asm volatile("red.global.add.v4.f32 [%0], {%1,%2,%3,%4};"
                 :: "l"(__cvta_generic_to_global(addr)),
                    "f"(a), "f"(b), "f"(c), "f"(d) : "memory");
}
__device__ __forceinline__ void ldsm_x4(uint32_t* r, uint32_t addr) {
    asm volatile("ldmatrix.sync.aligned.m8n8.x4.shared.b16 {%0,%1,%2,%3}, [%4];"
                 : "=r"(r[0]), "=r"(r[1]), "=r"(r[2]), "=r"(r[3]) : "r"(addr));
}
__device__ __forceinline__ void ldsm_x4t(uint32_t* r, uint32_t addr) {
    asm volatile("ldmatrix.sync.aligned.m8n8.x4.trans.shared.b16 {%0,%1,%2,%3}, [%4];"
                 : "=r"(r[0]), "=r"(r[1]), "=r"(r[2]), "=r"(r[3]) : "r"(addr));
}
__device__ __forceinline__ void mma16816(float* c, const uint32_t* a, const uint32_t* b) {
    asm volatile("mma.sync.aligned.m16n8k16.row.col.f32.bf16.bf16.f32 "
                 "{%0,%1,%2,%3}, {%4,%5,%6,%7}, {%8,%9}, {%0,%1,%2,%3};"
                 : "+f"(c[0]), "+f"(c[1]), "+f"(c[2]), "+f"(c[3])
                 : "r"(a[0]), "r"(a[1]), "r"(a[2]), "r"(a[3]),
                   "r"(b[0]), "r"(b[1]));
}
__device__ __forceinline__ uint32_t smem_u32(const void* p) {
    uint32_t a;
    asm("{ .reg .u64 t; cvta.to.shared.u64 t, %1; cvt.u32.u64 %0, t; }"
        : "=r"(a) : "l"(p));
    return a;
}

// smem layout (byte offsets into dynamic smem)
#define ASTRIDE 72
#define BSTRIDE 328
#define OFF_W1   0                       // 512 floats (2048 B)
#define OFF_BHI  2048                    // 64*328*2 = 41984 B
#define OFF_BLO  (OFF_BHI + 41984)
#define OFF_A    (OFF_BLO + 41984)       // 2 bufs x (hi 9216 + lo 9216)
#define ABUF_SZ  18432
#define DYN_BYTES (OFF_A + 2 * ABUF_SZ)  // 122880 B

// ---------------------------------------------------------------------------
// Kernel A: s1 = s @ W_lin_s ; v1 = einsum(v, W_lin_v). Zero A_s/A_v.
// ---------------------------------------------------------------------------
__global__ __launch_bounds__(256) void knodeA(
    const float* __restrict__ s, const float* __restrict__ v,
    const float* __restrict__ Wls, const float* __restrict__ Wlv)
{
    __shared__ float sWls[FF * FF], sWlv[FF * FF];
    __shared__ float sS[4 * FF], sV[4 * FF * 3];
    for (int i = threadIdx.x; i < FF * FF; i += blockDim.x) {
        sWls[i] = Wls[i];
        sWlv[i] = Wlv[i];
    }
    const int ngrp = NN / 4;
    for (int grp = blockIdx.x; grp < ngrp; grp += gridDim.x) {
        __syncthreads();
        int nbase = grp * 4;
        for (int i = threadIdx.x; i < 4 * FF; i += blockDim.x)
            sS[i] = s[nbase * FF + i];
        for (int i = threadIdx.x; i < 4 * FF * 3; i += blockDim.x)
            sV[i] = v[nbase * FF * 3 + i];
        __syncthreads();
        int nl = threadIdx.x >> 6, g = threadIdx.x & 63;
        int n = nbase + nl;
        const float* ps = sS + nl * FF;
        const float* pv = sV + nl * FF * 3;
        float as = 0.f, ax = 0.f, ay = 0.f, az = 0.f;
#pragma unroll 8
        for (int f = 0; f < FF; f++) {
            float wls = sWls[f * FF + g], wlv = sWlv[f * FF + g];
            as += ps[f] * wls;
            ax += pv[f * 3 + 0] * wlv;
            ay += pv[f * 3 + 1] * wlv;
            az += pv[f * 3 + 2] * wlv;
        }
        g_s1[n * FF + g] = as;
        g_v1[n * FF * 3 + g * 3 + 0] = ax;
        g_v1[n * FF * 3 + g * 3 + 1] = ay;
        g_v1[n * FF * 3 + g * 3 + 2] = az;
        g_As[n * FF + g] = 0.f;
        g_Av[n * FF * 3 + g * 3 + 0] = 0.f;
        g_Av[n * FF * 3 + g * 3 + 1] = 0.f;
        g_Av[n * FF * 3 + g * 3 + 2] = 0.f;
    }
}

// ---------------------------------------------------------------------------
// Kernel B: mma.sync bf16 hi/lo 3-pass GEMM, register-direct epilogue.
// W2 columns are PERMUTED within each 16-col group at staging time so that
// MMA thread qq's 4 accumulator slots per group map to 4 CONSECUTIVE logical
// f values -> epilogue scatters with red.v4 straight from registers.
// A tile double-buffered; 1 sync per tile.
// ---------------------------------------------------------------------------
__global__ __launch_bounds__(256, 1) void kedge5(
    const float* __restrict__ Y1, const float* __restrict__ efg,
    const int* __restrict__ senders, const int* __restrict__ receivers,
    const float* __restrict__ W_rad1, const float* __restrict__ W_rad2)
{
    extern __shared__ char dsm[];
    float* sW1 = (float*)(dsm + OFF_W1);
    const uint32_t uBhi = smem_u32(dsm + OFF_BHI);
    const uint32_t uBlo = smem_u32(dsm + OFF_BLO);
    const uint32_t uA0 = smem_u32(dsm + OFF_A);

    const int tid = threadIdx.x, wid = tid >> 5, lane = tid & 31;

    // --- one-time staging: W1 transposed ---
    for (int i = tid; i < RR * HH; i += 256) {
        int r = i / HH, j = i % HH;
        sW1[j * RR + r] = W_rad1[i];
    }
    // --- W2 -> B hi/lo bf16, column-PERMUTED within each 16-col group:
    //     logical offset l = 4q + 2*nt + b  stored at smem col nt*8 + 2q + b.
    //     For a logical col-pair m (=l>>1) in group: smem col = (m&1)*8+((m>>1)<<1).
    for (int i = tid; i < HH * (PP * FF / 2); i += 256) {
        int k = i / 160, n2 = i % 160;       // n2 = logical col-pair index
        int grp = n2 >> 3, m = n2 & 7;
        int sc = grp * 16 + (m & 1) * 8 + ((m >> 1) << 1);
        float w0 = W_rad2[k * (PP * FF) + 2 * n2];
        float w1 = W_rad2[k * (PP * FF) + 2 * n2 + 1];
        __nv_bfloat16 h0 = __float2bfloat16(w0);
        __nv_bfloat16 h1 = __float2bfloat16(w1);
        __nv_bfloat16 l0 = __float2bfloat16(w0 - __bfloat162float(h0));
        __nv_bfloat16 l1 = __float2bfloat16(w1 - __bfloat162float(h1));
        uint32_t off = (uint32_t)(k * BSTRIDE + sc) * 2;
        __nv_bfloat162 ph; ph.x = h0; ph.y = h1;
        __nv_bfloat162 pl; pl.x = l0; pl.y = l1;
        *(__nv_bfloat162*)(dsm + OFF_BHI + off) = ph;
        *(__nv_bfloat162*)(dsm + OFF_BLO + off) = pl;
    }

    const int eg = wid & 3, ch = wid >> 2;
    const int ebw = eg * 16;
    const int lm = lane >> 3, lr = lane & 7;
    const int arow = ebw + (lm & 1) * 8 + lr;
    const int acol0 = (lm >> 1) * 8;
    const int brow0 = (lm & 1) * 8 + lr;
    const int qq = lane & 3, eh = lane >> 2;

    auto stageA = [&](int t, int buf) {
        char* ab = dsm + OFF_A + buf * ABUF_SZ;
        int e = tid & 63, jq = tid >> 6;
        const float4* efp = (const float4*)(efg + (size_t)(t * TILE + e) * RR);
        float4 F0 = efp[0], F1 = efp[1];
#pragma unroll
        for (int jj = 0; jj < 16; jj += 2) {
            int j = jq * 16 + jj;
            const float4* wA = (const float4*)(sW1 + j * RR);
            float4 a0 = wA[0], a1 = wA[1], b0 = wA[2], b1 = wA[3];
            float z0 = F0.x * a0.x + F0.y * a0.y + F0.z * a0.z + F0.w * a0.w +
                       F1.x * a1.x + F1.y * a1.y + F1.z * a1.z + F1.w * a1.w;
            float z1 = F0.x * b0.x + F0.y * b0.y + F0.z * b0.z + F0.w * b0.w +
                       F1.x * b1.x + F1.y * b1.y + F1.z * b1.z + F1.w * b1.w;
            float h0f = __fdividef(z0, 1.f + __expf(-z0));
            float h1f = __fdividef(z1, 1.f + __expf(-z1));
            __nv_bfloat16 h0 = __float2bfloat16(h0f);
            __nv_bfloat16 h1 = __float2bfloat16(h1f);
            __nv_bfloat16 l0 = __float2bfloat16(h0f - __bfloat162float(h0));
            __nv_bfloat16 l1 = __float2bfloat16(h1f - __bfloat162float(h1));
            uint32_t off = (uint32_t)(e * ASTRIDE + j) * 2;
            __nv_bfloat162 ph; ph.x = h0; ph.y = h1;
            __nv_bfloat162 pl; pl.x = l0; pl.y = l1;
            *(__nv_bfloat162*)(ab + off) = ph;
            *(__nv_bfloat162*)(ab + 9216 + off) = pl;
        }
    };

    const int t0 = blockIdx.x;
    if (t0 < NTILES) stageA(t0, 0);
    __syncthreads();

    int it = 0;
    for (int t = t0; t < NTILES; t += gridDim.x, it++) {
        const int buf = it & 1;
        const uint32_t uAhi = uA0 + buf * ABUF_SZ;
        const uint32_t uAlo = uAhi + 9216;

        // ---- GEMM: acc[p][fs2][nt][4] ----
        float acc[PP][2][2][4];
#pragma unroll
        for (int p = 0; p < PP; p++)
#pragma unroll
            for (int fs2 = 0; fs2 < 2; fs2++)
#pragma unroll
                for (int nt = 0; nt < 2; nt++) {
                    acc[p][fs2][nt][0] = 0.f; acc[p][fs2][nt][1] = 0.f;
                    acc[p][fs2][nt][2] = 0.f; acc[p][fs2][nt][3] = 0.f;
                }
#pragma unroll
        for (int pass = 0; pass < 3; pass++) {
            uint32_t Ab = (pass == 2) ? uAlo : uAhi;
            uint32_t Bb = (pass == 1) ? uBlo : uBhi;
#pragma unroll
            for (int k = 0; k < 4; k++) {
                uint32_t a[4];
                ldsm_x4(a, Ab + (uint32_t)(arow * ASTRIDE + k * 16 + acol0) * 2);
#pragma unroll
                for (int p = 0; p < PP; p++) {
#pragma unroll
                    for (int fs2 = 0; fs2 < 2; fs2++) {
                        int col = p * 64 + ch * 32 + fs2 * 16;
                        uint32_t b[4];
                        ldsm_x4t(b, Bb + (uint32_t)((k * 16 + brow0) * BSTRIDE +
                                                    col + acol0) * 2);
                        mma16816(acc[p][fs2][0], a, b);
                        mma16816(acc[p][fs2][1], a, b + 2);
                    }
                }
            }
        }

        // ---- stage next tile's A (overlaps epilogue; consumed after sync) ----
        int tn = t + gridDim.x;
        if (tn < NTILES) stageA(tn, buf ^ 1);

        // ---- epilogue straight from accumulators (4 consecutive f/thread) ----
#pragma unroll
        for (int eidx = 0; eidx < 2; eidx++) {
            int e = t * TILE + ebw + eh + eidx * 8;
            int snd = senders[e], rcv = receivers[e];
            float Yx = Y1[e * 3 + 0], Yy = Y1[e * 3 + 1], Yz = Y1[e * 3 + 2];
            const float* sp = g_s1 + (size_t)snd * FF;
            const float* vp = g_v1 + (size_t)snd * FF * 3;
            float* Ap = g_As + (size_t)rcv * FF;
            float* Vp = g_Av + (size_t)rcv * FF * 3;

#pragma unroll
            for (int fs2 = 0; fs2 < 2; fs2++) {
                int f = ch * 32 + fs2 * 16 + 4 * qq;
                float4 ss = *(const float4*)(sp + f);
                const float* vq = vp + f * 3;
                float4 va = *(const float4*)(vq + 0);
                float4 vb = *(const float4*)(vq + 4);
                float4 vc = *(const float4*)(vq + 8);
                float ssf[4] = {ss.x, ss.y, ss.z, ss.w};
                float vx[4] = {va.x, va.w, vb.z, vc.y};
                float vy[4] = {va.y, vb.x, vb.w, vc.z};
                float vz[4] = {va.z, vb.y, vc.x, vc.w};
                float ms[4], mv[12];
#pragma unroll
                for (int j = 0; j < 4; j++) {
                    int nt = j >> 1, cb = j & 1;
                    float tw0 = acc[0][fs2][nt][eidx * 2 + cb];
                    float tw1 = acc[1][fs2][nt][eidx * 2 + cb];
                    float tw2 = acc[2][fs2][nt][eidx * 2 + cb];
                    float tw3 = acc[3][fs2][nt][eidx * 2 + cb];
                    float tw4 = acc[4][fs2][nt][eidx * 2 + cb];
                    float dot = vx[j] * Yx + vy[j] * Yy + vz[j] * Yz;
                    float cx = vy[j] * Yz - vz[j] * Yy;
                    float cy = vz[j] * Yx - vx[j] * Yz;
                    float cz = vx[j] * Yy - vy[j] * Yx;
                    ms[j] = tw0 * ssf[j] + tw1 * dot * INV_SQRT3;
                    float t2s = tw2 * ssf[j];
                    float t4 = tw4 * INV_SQRT2;
                    mv[3 * j + 0] = t2s * Yx + tw3 * vx[j] + t4 * cx;
                    mv[3 * j + 1] = t2s * Yy + tw3 * vy[j] + t4 * cy;
                    mv[3 * j + 2] = t2s * Yz + tw3 * vz[j] + t4 * cz;
                }
                red4(Ap + f, ms[0], ms[1], ms[2], ms[3]);
                float* wq = Vp + f * 3;
                red4(wq + 0, mv[0], mv[1], mv[2], mv[3]);
                red4(wq + 4, mv[4], mv[5], mv[6], mv[7]);
                red4(wq + 8, mv[8], mv[9], mv[10], mv[11]);
            }
        }
        __syncthreads();
    }
}

// ---------------------------------------------------------------------------
// Kernel C: node post: W_int + species skip + product basis + W_prod + readout
// ---------------------------------------------------------------------------
__global__ __launch_bounds__(256, 2) void knodeC(
    const float* __restrict__ s, const float* __restrict__ v,
    const int* __restrict__ spec,
    const float* __restrict__ W_sc_s, const float* __restrict__ W_sc_v,
    const float* __restrict__ W_int_s, const float* __restrict__ W_int_v,
    const float* __restrict__ w_prod_s, const float* __restrict__ w_prod_v,
    const float* __restrict__ W_prod_s, const float* __restrict__ W_prod_v,
    const float* __restrict__ W_read,
    float* __restrict__ out_node, float* __restrict__ out_s,
    float* __restrict__ out_v)
{
    extern __shared__ float sm[];
    float* sWis = sm;
    float* sWiv = sWis + FF * FF;
    float* sWps = sWiv + FF * FF;
    float* sWpv = sWps + FF * FF;
    float* sWr  = sWpv + FF * FF;
    float* sAs  = sWr + FF;
    float* sAv  = sAs + 4 * FF;
    float* sSin = sAv + 4 * FF * 3;
    float* sVin = sSin + 4 * FF;
    float* sBs  = sVin + 4 * FF * 3;
    float* sBv  = sBs + 4 * FF;
    float* sRed = sBv + 4 * FF * 3;
    __shared__ int sSpec[4];

    for (int i = threadIdx.x; i < FF * FF; i += blockDim.x) {
        sWis[i] = W_int_s[i];
        sWiv[i] = W_int_v[i];
        sWps[i] = W_prod_s[i];
        sWpv[i] = W_prod_v[i];
    }
    if (threadIdx.x < FF) sWr[threadIdx.x] = W_read[threadIdx.x];

    const int ngrp = NN / 4;
    for (int grp = blockIdx.x; grp < ngrp; grp += gridDim.x) {
        __syncthreads();
        int nbase = grp * 4;
        for (int i = threadIdx.x; i < 4 * FF; i += blockDim.x) {
            sAs[i] = g_As[nbase * FF + i];
            sSin[i] = s[nbase * FF + i];
        }
        for (int i = threadIdx.x; i < 4 * FF * 3; i += blockDim.x) {
            sAv[i] = g_Av[nbase * FF * 3 + i];
            sVin[i] = v[nbase * FF * 3 + i];
        }
        if (threadIdx.x < 4) sSpec[threadIdx.x] = spec[nbase + threadIdx.x];
        __syncthreads();

        int nl = threadIdx.x >> 6, g = threadIdx.x & 63;
        int n = nbase + nl;
        int sp = sSpec[nl];
        const float* Wscs = W_sc_s + sp * FF * FF;
        const float* Wscv = W_sc_v + sp * FF * FF;
        const float* pAs = sAs + nl * FF;
        const float* pAv = sAv + nl * FF * 3;
        const float* pS = sSin + nl * FF;
        const float* pV = sVin + nl * FF * 3;

        float as = 0.f, avx = 0.f, avy = 0.f, avz = 0.f;
        float scs = 0.f, scvx = 0.f, scvy = 0.f, scvz = 0.f;
#pragma unroll 4
        for (int f = 0; f < FF; f++) {
            float wis = sWis[f * FF + g], wiv = sWiv[f * FF + g];
            float wss = __ldg(Wscs + f * FF + g);
            float wsv = __ldg(Wscv + f * FF + g);
            as += pAs[f] * wis;
            avx += pAv[f * 3 + 0] * wiv;
            avy += pAv[f * 3 + 1] * wiv;
            avz += pAv[f * 3 + 2] * wiv;
            scs += pS[f] * wss;
            scvx += pV[f * 3 + 0] * wsv;
            scvy += pV[f * 3 + 1] * wsv;
            scvz += pV[f * 3 + 2] * wsv;
        }
        const float inv = 0.25f;
        as *= inv; avx *= inv; avy *= inv; avz *= inv;

        const float* wps = w_prod_s + sp * 5 * FF;
        const float* wpv = w_prod_v + sp * 4 * FF;
        float d = avx * avx + avy * avy + avz * avz;
        float as2 = as * as;
        float Bs = wps[0 * FF + g] * as + wps[1 * FF + g] * as2 +
                   wps[2 * FF + g] * d + wps[3 * FF + g] * as2 * as +
                   wps[4 * FF + g] * as * d;
        float gv = wpv[0 * FF + g] + wpv[1 * FF + g] * as +
                   wpv[2 * FF + g] * as2 + wpv[3 * FF + g] * d;
        sBs[nl * FF + g] = Bs;
        sBv[nl * FF * 3 + g * 3 + 0] = gv * avx;
        sBv[nl * FF * 3 + g * 3 + 1] = gv * avy;
        sBv[nl * FF * 3 + g * 3 + 2] = gv * avz;
        __syncthreads();

        const float* pBs = sBs + nl * FF;
        const float* pBv = sBv + nl * FF * 3;
        float so = scs, vox = scvx, voy = scvy, voz = scvz;
#pragma unroll 4
        for (int f = 0; f < FF; f++) {
            float wp = sWps[f * FF + g], wv = sWpv[f * FF + g];
            so += pBs[f] * wp;
            vox += pBv[f * 3 + 0] * wv;
            voy += pBv[f * 3 + 1] * wv;
            voz += pBv[f * 3 + 2] * wv;
        }
        out_s[n * FF + g] = so;
        out_v[n * FF * 3 + g * 3 + 0] = vox;
        out_v[n * FF * 3 + g * 3 + 1] = voy;
        out_v[n * FF * 3 + g * 3 + 2] = voz;

        float r = so * sWr[g];
#pragma unroll
        for (int o = 16; o > 0; o >>= 1) r += __shfl_down_sync(0xffffffffu, r, o);
        if ((threadIdx.x & 31) == 0) sRed[threadIdx.x >> 5] = r;
        __syncthreads();
        if ((threadIdx.x & 63) == 0)
            out_node[n] = sRed[threadIdx.x >> 5] + sRed[(threadIdx.x >> 5) + 1];
    }
}

// ---------------------------------------------------------------------------
extern "C" void kernel_launch(void* const* d_in, const int* in_sizes, int n_in,
                              void* d_out, int out_size)
{
    const float* s    = (const float*)d_in[0];
    const float* v    = (const float*)d_in[1];
    const float* Y1   = (const float*)d_in[2];
    const float* ef   = (const float*)d_in[3];
    const int*   spec = (const int*)d_in[4];
    const int*   snd  = (const int*)d_in[5];
    const int*   rcv  = (const int*)d_in[6];
    const float* Wls  = (const float*)d_in[7];
    const float* Wlv  = (const float*)d_in[8];
    const float* Wscs = (const float*)d_in[9];
    const float* Wscv = (const float*)d_in[10];
    const float* Wr1  = (const float*)d_in[11];
    const float* Wr2  = (const float*)d_in[12];
    const float* Wis  = (const float*)d_in[13];
    const float* Wiv  = (const float*)d_in[14];
    const float* wps  = (const float*)d_in[15];
    const float* wpv  = (const float*)d_in[16];
    const float* Wps  = (const float*)d_in[17];
    const float* Wpv  = (const float*)d_in[18];
    const float* Wrd  = (const float*)d_in[19];

    float* out = (float*)d_out;
    float* out_node = out;
    float* out_s = out + NN;
    float* out_v = out + NN + NN * FF;

    const int smemC = (4 * FF * FF + FF + 4 * FF * 2 + 4 * FF * 3 * 2 +
                       4 * FF + 4 * FF * 3 + 8) * (int)sizeof(float);
    cudaFuncSetAttribute(kedge5, cudaFuncAttributeMaxDynamicSharedMemorySize, DYN_BYTES);
    cudaFuncSetAttribute(knodeC, cudaFuncAttributeMaxDynamicSharedMemorySize, smemC);

    knodeA<<<592, 256>>>(s, v, Wls, Wlv);
    kedge5<<<152, 256, DYN_BYTES>>>(Y1, ef, snd, rcv, Wr1, Wr2);
    knodeC<<<296, 256, smemC>>>(s, v, spec, Wscs, Wscv, Wis, Wiv,
                                wps, wpv, Wps, Wpv, Wrd,
                                out_node, out_s, out_v);
}